// round 1
// baseline (speedup 1.0000x reference)
#include <cuda_runtime.h>
#include <cstdint>

// ---------------------------------------------------------------------------
// GraphNeuralNetwork: 4 sparse layers, DEG=64 parents per node, B=512.
// h kept transposed [node, batch] in fp32 ping-pong buffers.
// Per layer: gather from SMEM-staged 512-row chunks of h, edges pre-partitioned
// by chunk by a prep kernel (warp-per-node ballot partition).
// ---------------------------------------------------------------------------

#define BATCH   512
#define COLS    64          // batch columns per CTA (warp covers all 64, float2/lane)
#define CHUNK   512         // source rows per SMEM chunk
#define THREADS 512
#define EMAX    131072      // max edges per layer (2048*64)

__device__ float g_hA[2048 * 512];
__device__ float g_hB[2048 * 512];
__device__ int2  g_edges[4][EMAX];          // .x = chunk-local src, .y = weight bits
__device__ int   g_cnt[4][2048 * 4];        // per (node, chunk) edge counts

// ---------------------------------------------------------------------------
// Transpose x [512,512] row-major -> [node, batch]
// ---------------------------------------------------------------------------
__global__ void transpose512(const float* __restrict__ x, float* __restrict__ out) {
    __shared__ float t[32][33];
    int bx = blockIdx.x * 32, by = blockIdx.y * 32;
    int tx = threadIdx.x, ty = threadIdx.y;
#pragma unroll
    for (int i = 0; i < 32; i += 8)
        t[ty + i][tx] = x[(by + ty + i) * 512 + bx + tx];
    __syncthreads();
#pragma unroll
    for (int i = 0; i < 32; i += 8)
        out[(bx + ty + i) * 512 + by + tx] = t[tx][ty + i];
}

// ---------------------------------------------------------------------------
// Prep: warp-per-node stable partition of its 64 edges into CHUNK=512 buckets.
// Stores chunk-local source index + weight bits, and per-chunk counts.
// For layers with n_prev=512 all edges land in chunk 0 (s>>9 == 0) — uniform.
// ---------------------------------------------------------------------------
__global__ void prep_edges(const int* __restrict__ src, const float* __restrict__ w,
                           int n_curr, int2* __restrict__ ed, int* __restrict__ cnt) {
    int gw   = (blockIdx.x * blockDim.x + threadIdx.x) >> 5;
    int lane = threadIdx.x & 31;
    if (gw >= n_curr) return;
    int base = gw << 6;

    int   s0 = src[base + lane],      s1 = src[base + 32 + lane];
    float v0 = w[base + lane];        float v1 = w[base + 32 + lane];
    int   c0 = s0 >> 9,               c1 = s1 >> 9;

    unsigned m0[4], m1[4];
#pragma unroll
    for (int c = 0; c < 4; c++) {
        m0[c] = __ballot_sync(0xffffffffu, c0 == c);
        m1[c] = __ballot_sync(0xffffffffu, c1 == c);
    }
    int off[4]; int run = 0;
#pragma unroll
    for (int c = 0; c < 4; c++) { off[c] = run; run += __popc(m0[c]) + __popc(m1[c]); }

    unsigned lt = (1u << lane) - 1u;
    int p0 = off[c0] + __popc(m0[c0] & lt);
    int p1 = off[c1] + __popc(m0[c1]) + __popc(m1[c1] & lt);

    ed[base + p0] = make_int2(s0 & (CHUNK - 1), __float_as_int(v0));
    ed[base + p1] = make_int2(s1 & (CHUNK - 1), __float_as_int(v1));
    if (lane < 4) cnt[(gw << 2) + lane] = __popc(m0[lane]) + __popc(m1[lane]);
}

// ---------------------------------------------------------------------------
// Layer kernel. CTA: COLS batch cols x NPC nodes. Warp = 1 node x 64 cols.
// SMEM: h chunk [CHUNK x COLS] fp32 (128KB) + NPC*64 edges + NPC*5 offsets.
// ---------------------------------------------------------------------------
template <int NPC, int NCHUNK, bool RELU, bool FINAL>
__global__ __launch_bounds__(THREADS, 1)
void layer_kernel(const float* __restrict__ h_in,
                  const int2*  __restrict__ gedges,
                  const int*   __restrict__ gcnt,
                  const float* __restrict__ bias,
                  float*       __restrict__ out) {
    constexpr int NPW = NPC / (THREADS / 32);   // nodes per warp
    extern __shared__ char smem[];
    float* sh = (float*)smem;                                   // CHUNK*COLS floats
    int2*  se = (int2*)(smem + CHUNK * COLS * 4);               // NPC*64 edges
    int*   so = (int*)(smem + CHUNK * COLS * 4 + NPC * 64 * 8); // NPC*5 offsets

    const int tid  = threadIdx.x;
    const int lane = tid & 31, warp = tid >> 5;
    const int ct0      = blockIdx.x * COLS;
    const int nodeBase = blockIdx.y * NPC;

    // Stage this CTA's edges (contiguous block) + per-node chunk offsets.
    for (int i = tid; i < NPC * 64; i += THREADS)
        se[i] = gedges[nodeBase * 64 + i];
    if (tid < NPC) {
        int r = 0;
#pragma unroll
        for (int c = 0; c < 4; c++) {
            so[tid * 5 + c] = r;
            r += gcnt[(nodeBase + tid) * 4 + c];
        }
        so[tid * 5 + 4] = r;   // == 64
    }

    float2 acc[NPW];
#pragma unroll
    for (int i = 0; i < NPW; i++) acc[i] = make_float2(0.f, 0.f);

    for (int c = 0; c < NCHUNK; c++) {
        __syncthreads();   // previous-pass gathers done before overwrite
        // Fill h chunk: rows [c*CHUNK, c*CHUNK+CHUNK) x cols [ct0, ct0+COLS)
        const float4* gsrc = (const float4*)(h_in + (size_t)c * CHUNK * BATCH + ct0);
#pragma unroll
        for (int i = tid; i < CHUNK * (COLS / 4); i += THREADS) {
            int row = i >> 4, q = i & 15;     // COLS/4 == 16
            ((float4*)sh)[i] = gsrc[row * (BATCH / 4) + q];
        }
        __syncthreads();

#pragma unroll
        for (int i = 0; i < NPW; i++) {
            int n  = warp * NPW + i;
            int k1 = so[n * 5 + c + 1];
            float2 a = acc[i];
            for (int k = so[n * 5 + c]; k < k1; k++) {
                int2  ed = se[n * 64 + k];                  // broadcast LDS.64
                float wt = __int_as_float(ed.y);
                float2 h2 = *(const float2*)&sh[ed.x * COLS + lane * 2];
                a.x += h2.x * wt;
                a.y += h2.y * wt;
            }
            acc[i] = a;
        }
    }

#pragma unroll
    for (int i = 0; i < NPW; i++) {
        int n = warp * NPW + i;
        int j = nodeBase + n;
        float bv = bias[j];
        float vx = acc[i].x + bv, vy = acc[i].y + bv;
        if (RELU) { vx = fmaxf(vx, 0.f); vy = fmaxf(vy, 0.f); }
        if (!FINAL) {
            *(float2*)&out[(size_t)j * BATCH + ct0 + lane * 2] = make_float2(vx, vy);
        } else {
            // d_out is [B, 512] row-major
            int cidx = ct0 + lane * 2;
            out[(size_t)cidx * 512 + j]       = vx;
            out[(size_t)(cidx + 1) * 512 + j] = vy;
        }
    }
}

// ---------------------------------------------------------------------------
// Host launch
// ---------------------------------------------------------------------------
extern "C" void kernel_launch(void* const* d_in, const int* in_sizes, int n_in,
                              void* d_out, int out_size) {
    (void)n_in; (void)out_size;

    const float* x;
    const float* w[4];
    const float* b[4];
    const int*   src[4];

    if (in_sizes[0] == 2048) {
        // alphabetical metadata order: b0..b3, dst0..dst3, src0..src3, w0..w3, x
        for (int l = 0; l < 4; l++) {
            b[l]   = (const float*)d_in[l];
            src[l] = (const int*)d_in[8 + l];
            w[l]   = (const float*)d_in[12 + l];
        }
        x = (const float*)d_in[16];
    } else if (in_sizes[7] == 32768) {
        // reference-signature order: x, w0,b0, w1,b1, w2,b2, w3,b3, src0,dst0, ...
        x = (const float*)d_in[0];
        for (int l = 0; l < 4; l++) {
            w[l]   = (const float*)d_in[1 + 2 * l];
            b[l]   = (const float*)d_in[2 + 2 * l];
            src[l] = (const int*)d_in[9 + 2 * l];
        }
    } else {
        // setup_inputs dict order: x, (w,b,src,dst) per layer
        x = (const float*)d_in[0];
        for (int l = 0; l < 4; l++) {
            w[l]   = (const float*)d_in[1 + 4 * l];
            b[l]   = (const float*)d_in[2 + 4 * l];
            src[l] = (const int*)d_in[3 + 4 * l];
        }
    }

    float* hA; float* hB; int2* ed; int* cnt;
    cudaGetSymbolAddress((void**)&hA,  g_hA);
    cudaGetSymbolAddress((void**)&hB,  g_hB);
    cudaGetSymbolAddress((void**)&ed,  g_edges);
    cudaGetSymbolAddress((void**)&cnt, g_cnt);

    constexpr int SMEM_BIG   = CHUNK * COLS * 4 + 128 * 64 * 8 + 128 * 5 * 4; // 199168
    constexpr int SMEM_SMALL = CHUNK * COLS * 4 +  32 * 64 * 8 +  32 * 5 * 4; // 148096

    cudaFuncSetAttribute(layer_kernel<128, 1, true,  false>,
                         cudaFuncAttributeMaxDynamicSharedMemorySize, SMEM_BIG);
    cudaFuncSetAttribute(layer_kernel<128, 4, true,  false>,
                         cudaFuncAttributeMaxDynamicSharedMemorySize, SMEM_BIG);
    cudaFuncSetAttribute(layer_kernel<32,  4, false, true>,
                         cudaFuncAttributeMaxDynamicSharedMemorySize, SMEM_SMALL);

    // 1) transpose x into hA (node-major)
    transpose512<<<dim3(16, 16), dim3(32, 8)>>>(x, hA);

    // 2) partition edges per node by 512-row chunk
    prep_edges<<<256, 256>>>(src[0], w[0], 2048, ed + 0 * EMAX, cnt + 0 * 2048 * 4);
    prep_edges<<<256, 256>>>(src[1], w[1], 2048, ed + 1 * EMAX, cnt + 1 * 2048 * 4);
    prep_edges<<<256, 256>>>(src[2], w[2], 2048, ed + 2 * EMAX, cnt + 2 * 2048 * 4);
    prep_edges<<< 64, 256>>>(src[3], w[3],  512, ed + 3 * EMAX, cnt + 3 * 2048 * 4);

    // 3) layers
    layer_kernel<128, 1, true, false><<<dim3(8, 16), THREADS, SMEM_BIG>>>(
        hA, ed + 0 * EMAX, cnt + 0 * 2048 * 4, b[0], hB);
    layer_kernel<128, 4, true, false><<<dim3(8, 16), THREADS, SMEM_BIG>>>(
        hB, ed + 1 * EMAX, cnt + 1 * 2048 * 4, b[1], hA);
    layer_kernel<128, 4, true, false><<<dim3(8, 16), THREADS, SMEM_BIG>>>(
        hA, ed + 2 * EMAX, cnt + 2 * 2048 * 4, b[2], hB);
    layer_kernel<32, 4, false, true><<<dim3(8, 16), THREADS, SMEM_SMALL>>>(
        hB, ed + 3 * EMAX, cnt + 3 * 2048 * 4, b[3], (float*)d_out);
}

// round 2
// speedup vs baseline: 1.0832x; 1.0832x over previous
#include <cuda_runtime.h>
#include <cstdint>

// ---------------------------------------------------------------------------
// GraphNeuralNetwork: 4 sparse layers, DEG=64 parents per node, B=512.
// h kept transposed [node, batch] in fp32 ping-pong buffers.
// Round 2: fused transpose+prep (1 launch), unrolled gather loop with
// pre-scaled byte offsets, packed fma.rn.f32x2.
// ---------------------------------------------------------------------------

#define BATCH   512
#define COLS    64          // batch columns per CTA (warp covers all 64, float2/lane)
#define CHUNK   512         // source rows per SMEM chunk
#define THREADS 512
#define EMAX    131072      // max edges per layer (2048*64)

__device__ float g_hA[2048 * 512];
__device__ float g_hB[2048 * 512];
__device__ int2  g_edges[4][EMAX];          // .x = chunk-local src byte offset, .y = weight bits
__device__ int   g_cnt[4][2048 * 4];        // per (node, chunk) edge counts

// ---------------------------------------------------------------------------
// Fused prep: transpose x (blocks 0..255) + edge partition for all 4 layers
// (blocks 256..1087). One launch, big grid -> DRAM latency hidden.
// ---------------------------------------------------------------------------
__device__ __forceinline__ void prep_node_warp(
    const int* __restrict__ src, const float* __restrict__ w,
    int gw, int lane, int2* __restrict__ ed, int* __restrict__ cnt) {
    int base = gw << 6;

    int   s0 = src[base + lane];      int   s1 = src[base + 32 + lane];
    float v0 = w[base + lane];        float v1 = w[base + 32 + lane];
    int   c0 = s0 >> 9,               c1 = s1 >> 9;

    unsigned m0[4], m1[4];
#pragma unroll
    for (int c = 0; c < 4; c++) {
        m0[c] = __ballot_sync(0xffffffffu, c0 == c);
        m1[c] = __ballot_sync(0xffffffffu, c1 == c);
    }
    int off[4]; int run = 0;
#pragma unroll
    for (int c = 0; c < 4; c++) { off[c] = run; run += __popc(m0[c]) + __popc(m1[c]); }

    unsigned lt = (1u << lane) - 1u;
    int p0 = off[c0] + __popc(m0[c0] & lt);
    int p1 = off[c1] + __popc(m0[c1]) + __popc(m1[c1] & lt);

    // store byte offset into the staged chunk: (s & 511) * COLS * 4
    ed[base + p0] = make_int2((s0 & (CHUNK - 1)) << 8, __float_as_int(v0));
    ed[base + p1] = make_int2((s1 & (CHUNK - 1)) << 8, __float_as_int(v1));
    if (lane < 4) cnt[(gw << 2) + lane] = __popc(m0[lane]) + __popc(m1[lane]);
}

__global__ void fused_prep(
    const float* __restrict__ x, float* __restrict__ hA,
    const int* __restrict__ src0, const float* __restrict__ w0,
    const int* __restrict__ src1, const float* __restrict__ w1,
    const int* __restrict__ src2, const float* __restrict__ w2,
    const int* __restrict__ src3, const float* __restrict__ w3,
    int2* __restrict__ ed, int* __restrict__ cnt) {
    __shared__ float t[32][33];
    int b   = blockIdx.x;
    int tid = threadIdx.x;

    if (b < 256) {
        // transpose x [512,512] -> hA [node, batch]
        int bx = (b & 15) * 32, by = (b >> 4) * 32;
        int tx = tid & 31, ty = tid >> 5;       // 32 x 8
#pragma unroll
        for (int i = 0; i < 32; i += 8)
            t[ty + i][tx] = x[(by + ty + i) * 512 + bx + tx];
        __syncthreads();
#pragma unroll
        for (int i = 0; i < 32; i += 8)
            hA[(bx + ty + i) * 512 + by + tx] = t[tx][ty + i];
        return;
    }

    int lane = tid & 31;
    int warp = tid >> 5;                        // 8 warps/block
    int pb   = b - 256;
    if (pb < 256) {
        prep_node_warp(src0, w0, pb * 8 + warp, lane, ed + 0 * EMAX, cnt + 0 * 8192);
    } else if (pb < 512) {
        prep_node_warp(src1, w1, (pb - 256) * 8 + warp, lane, ed + 1 * EMAX, cnt + 1 * 8192);
    } else if (pb < 768) {
        prep_node_warp(src2, w2, (pb - 512) * 8 + warp, lane, ed + 2 * EMAX, cnt + 2 * 8192);
    } else {
        int gw = (pb - 768) * 8 + warp;         // 64 blocks x 8 = 512 nodes
        prep_node_warp(src3, w3, gw, lane, ed + 3 * EMAX, cnt + 3 * 8192);
    }
}

// ---------------------------------------------------------------------------
// Layer kernel. CTA: COLS batch cols x NPC nodes. Warp = 1 node x 64 cols.
// SMEM: h chunk [CHUNK x COLS] fp32 (128KB) + NPC*64 edges + NPC*5 offsets.
// ---------------------------------------------------------------------------
template <int NPC, int NCHUNK, bool RELU, bool FINAL>
__global__ __launch_bounds__(THREADS, 1)
void layer_kernel(const float* __restrict__ h_in,
                  const int2*  __restrict__ gedges,
                  const int*   __restrict__ gcnt,
                  const float* __restrict__ bias,
                  float*       __restrict__ out) {
    constexpr int NPW = NPC / (THREADS / 32);   // nodes per warp
    extern __shared__ char smem[];
    float* sh = (float*)smem;                                   // CHUNK*COLS floats
    int2*  se = (int2*)(smem + CHUNK * COLS * 4);               // NPC*64 edges
    int*   so = (int*)(smem + CHUNK * COLS * 4 + NPC * 64 * 8); // NPC*5 offsets

    const int tid  = threadIdx.x;
    const int lane = tid & 31, warp = tid >> 5;
    const int ct0      = blockIdx.x * COLS;
    const int nodeBase = blockIdx.y * NPC;

    // Stage this CTA's edges (contiguous block) + per-node chunk offsets.
    for (int i = tid; i < NPC * 64; i += THREADS)
        se[i] = gedges[nodeBase * 64 + i];
    if (tid < NPC) {
        int r = 0;
#pragma unroll
        for (int c = 0; c < 4; c++) {
            so[tid * 5 + c] = r;
            r += gcnt[(nodeBase + tid) * 4 + c];
        }
        so[tid * 5 + 4] = r;   // == 64
    }

    // per-lane base pointer into the staged chunk (lane covers 2 cols)
    const char* shb = (const char*)sh + lane * 8;

    unsigned long long acc[NPW];
#pragma unroll
    for (int i = 0; i < NPW; i++) acc[i] = 0ull;

    for (int c = 0; c < NCHUNK; c++) {
        __syncthreads();   // previous-pass gathers done before overwrite
        // Fill h chunk: rows [c*CHUNK, +CHUNK) x cols [ct0, +COLS)
        const float4* gsrc = (const float4*)(h_in + (size_t)c * CHUNK * BATCH + ct0);
#pragma unroll
        for (int i = tid; i < CHUNK * (COLS / 4); i += THREADS) {
            int row = i >> 4, q = i & 15;     // COLS/4 == 16
            ((float4*)sh)[i] = gsrc[row * (BATCH / 4) + q];
        }
        __syncthreads();

#pragma unroll
        for (int i = 0; i < NPW; i++) {
            int n  = warp * NPW + i;
            int k0 = so[n * 5 + c];
            int k1 = so[n * 5 + c + 1];
            unsigned long long a = acc[i];
            const int2* sen = se + n * 64;
#pragma unroll 4
            for (int k = k0; k < k1; k++) {
                int2 ed = sen[k];                               // broadcast LDS.64
                unsigned long long h2 = *(const unsigned long long*)(shb + ed.x);
                unsigned long long ww;
                asm("mov.b64 %0, {%1, %1};" : "=l"(ww) : "r"(ed.y));
                asm("fma.rn.f32x2 %0, %1, %2, %0;" : "+l"(a) : "l"(h2), "l"(ww));
            }
            acc[i] = a;
        }
    }

#pragma unroll
    for (int i = 0; i < NPW; i++) {
        int n = warp * NPW + i;
        int j = nodeBase + n;
        float bv = bias[j];
        unsigned lo = (unsigned)(acc[i] & 0xffffffffull);
        unsigned hi = (unsigned)(acc[i] >> 32);
        float vx = __uint_as_float(lo) + bv;
        float vy = __uint_as_float(hi) + bv;
        if (RELU) { vx = fmaxf(vx, 0.f); vy = fmaxf(vy, 0.f); }
        if (!FINAL) {
            *(float2*)&out[(size_t)j * BATCH + ct0 + lane * 2] = make_float2(vx, vy);
        } else {
            // d_out is [B, 512] row-major
            int cidx = ct0 + lane * 2;
            out[(size_t)cidx * 512 + j]       = vx;
            out[(size_t)(cidx + 1) * 512 + j] = vy;
        }
    }
}

// ---------------------------------------------------------------------------
// Host launch
// ---------------------------------------------------------------------------
extern "C" void kernel_launch(void* const* d_in, const int* in_sizes, int n_in,
                              void* d_out, int out_size) {
    (void)n_in; (void)out_size;

    const float* x;
    const float* w[4];
    const float* b[4];
    const int*   src[4];

    if (in_sizes[0] == 2048) {
        // alphabetical metadata order: b0..b3, dst0..dst3, src0..src3, w0..w3, x
        for (int l = 0; l < 4; l++) {
            b[l]   = (const float*)d_in[l];
            src[l] = (const int*)d_in[8 + l];
            w[l]   = (const float*)d_in[12 + l];
        }
        x = (const float*)d_in[16];
    } else if (in_sizes[7] == 32768) {
        // reference-signature order: x, w0,b0, w1,b1, w2,b2, w3,b3, src0,dst0, ...
        x = (const float*)d_in[0];
        for (int l = 0; l < 4; l++) {
            w[l]   = (const float*)d_in[1 + 2 * l];
            b[l]   = (const float*)d_in[2 + 2 * l];
            src[l] = (const int*)d_in[9 + 2 * l];
        }
    } else {
        // setup_inputs dict order: x, (w,b,src,dst) per layer
        x = (const float*)d_in[0];
        for (int l = 0; l < 4; l++) {
            w[l]   = (const float*)d_in[1 + 4 * l];
            b[l]   = (const float*)d_in[2 + 4 * l];
            src[l] = (const int*)d_in[3 + 4 * l];
        }
    }

    float* hA; float* hB; int2* ed; int* cnt;
    cudaGetSymbolAddress((void**)&hA,  g_hA);
    cudaGetSymbolAddress((void**)&hB,  g_hB);
    cudaGetSymbolAddress((void**)&ed,  g_edges);
    cudaGetSymbolAddress((void**)&cnt, g_cnt);

    constexpr int SMEM_BIG   = CHUNK * COLS * 4 + 128 * 64 * 8 + 128 * 5 * 4; // 199168
    constexpr int SMEM_SMALL = CHUNK * COLS * 4 +  32 * 64 * 8 +  32 * 5 * 4; // 148096

    cudaFuncSetAttribute(layer_kernel<128, 1, true,  false>,
                         cudaFuncAttributeMaxDynamicSharedMemorySize, SMEM_BIG);
    cudaFuncSetAttribute(layer_kernel<128, 4, true,  false>,
                         cudaFuncAttributeMaxDynamicSharedMemorySize, SMEM_BIG);
    cudaFuncSetAttribute(layer_kernel<32,  4, false, true>,
                         cudaFuncAttributeMaxDynamicSharedMemorySize, SMEM_SMALL);

    // 1) fused: transpose x -> hA  +  partition all 4 layers' edges
    fused_prep<<<1088, 256>>>(x, hA,
                              src[0], w[0], src[1], w[1],
                              src[2], w[2], src[3], w[3],
                              ed, cnt);

    // 2) layers
    layer_kernel<128, 1, true, false><<<dim3(8, 16), THREADS, SMEM_BIG>>>(
        hA, ed + 0 * EMAX, cnt + 0 * 8192, b[0], hB);
    layer_kernel<128, 4, true, false><<<dim3(8, 16), THREADS, SMEM_BIG>>>(
        hB, ed + 1 * EMAX, cnt + 1 * 8192, b[1], hA);
    layer_kernel<128, 4, true, false><<<dim3(8, 16), THREADS, SMEM_BIG>>>(
        hA, ed + 2 * EMAX, cnt + 2 * 8192, b[2], hB);
    layer_kernel<32, 4, false, true><<<dim3(8, 16), THREADS, SMEM_SMALL>>>(
        hB, ed + 3 * EMAX, cnt + 3 * 8192, b[3], (float*)d_out);
}